// round 13
// baseline (speedup 1.0000x reference)
#include <cuda_runtime.h>
#include <cuda_bf16.h>
#include <cstdint>

#define MAX_N 50432
#define DD 64

__device__ __align__(16) float g_summed[MAX_N * DD];  // sum of relu(h_e) per dst node
__device__ float g_counts[MAX_N];
__device__ __align__(16) float g_hx[MAX_N * DD];   // x @ w1a[0:64] + b1a
__device__ __align__(16) float g_hx2[MAX_N * DD];  // x @ w2a[0:64] + b2a

// ---------- tf32 + mma helpers ----------
__device__ __forceinline__ uint32_t f2tf32(float f) {
    uint32_t r;
    asm("cvt.rna.tf32.f32 %0, %1;" : "=r"(r) : "f"(f));
    return r;
}
// D(16x8,f32) += A(16x8,tf32,row) * B(8x8,tf32,col)
__device__ __forceinline__ void mma_tf32(float* d, const uint32_t* a,
                                         uint32_t b0, uint32_t b1) {
    asm volatile(
        "mma.sync.aligned.m16n8k8.row.col.f32.tf32.tf32.f32 "
        "{%0,%1,%2,%3}, {%4,%5,%6,%7}, {%8,%9}, {%0,%1,%2,%3};"
        : "+f"(d[0]), "+f"(d[1]), "+f"(d[2]), "+f"(d[3])
        : "r"(a[0]), "r"(a[1]), "r"(a[2]), "r"(a[3]), "r"(b0), "r"(b1));
}

// Warp GEMM: C[32x64] += A(se: 32 rows x 64 k, stride 68) * B(sw: [k][n] stride 72)^T
__device__ __forceinline__ void warp_gemm(const uint32_t* se, const uint32_t* sw,
                                          int gid, int tig, float c[2][8][4]) {
#pragma unroll
    for (int kt = 0; kt < 8; kt++) {
        uint32_t a[2][4];
#pragma unroll
        for (int mt = 0; mt < 2; mt++) {
            int r0 = mt * 16 + gid;
            a[mt][0] = se[r0 * 68 + kt * 8 + tig];
            a[mt][1] = se[(r0 + 8) * 68 + kt * 8 + tig];
            a[mt][2] = se[r0 * 68 + kt * 8 + tig + 4];
            a[mt][3] = se[(r0 + 8) * 68 + kt * 8 + tig + 4];
        }
#pragma unroll
        for (int j = 0; j < 8; j++) {
            uint32_t b0 = sw[(kt * 8 + tig) * 72 + j * 8 + gid];
            uint32_t b1 = sw[(kt * 8 + tig + 4) * 72 + j * 8 + gid];
            mma_tf32(c[0][j], a[0], b0, b1);
            mma_tf32(c[1][j], a[1], b0, b1);
        }
    }
}

__device__ __forceinline__ void zero_c(float c[2][8][4]) {
#pragma unroll
    for (int mt = 0; mt < 2; mt++)
#pragma unroll
        for (int j = 0; j < 8; j++)
#pragma unroll
            for (int r = 0; r < 4; r++) c[mt][j][r] = 0.f;
}

// ---------- zero scratch ----------
__global__ void zero_summed(int n_f4) {
    int i = blockIdx.x * blockDim.x + threadIdx.x;
    int stride = gridDim.x * blockDim.x;
    float4 z = make_float4(0.f, 0.f, 0.f, 0.f);
    for (int j = i; j < n_f4; j += stride) ((float4*)g_summed)[j] = z;
}
__global__ void zero_counts(int n) {
    int i = blockIdx.x * blockDim.x + threadIdx.x;
    if (i < n) g_counts[i] = 0.f;
}

// ================= hx kernel: hx = x@w1a_top + b1a, hx2 = x@w2a_top + b2a =================
#define HX_SW1 0
#define HX_SW2 18432
#define HX_SB 36864
#define HX_SB2 37120
#define HX_SE 37376
#define HX_SMEM (HX_SE + 8 * 32 * 68 * 4)  // 107008

__global__ void __launch_bounds__(256, 2) hx_mma_kernel(
    const float* __restrict__ x,
    const float* __restrict__ w1a, const float* __restrict__ b1a,
    const float* __restrict__ w2a, const float* __restrict__ b2a,
    int N) {
    extern __shared__ __align__(16) char dsm[];
    uint32_t* sw1 = (uint32_t*)(dsm + HX_SW1);
    uint32_t* sw2 = (uint32_t*)(dsm + HX_SW2);
    float* sb1 = (float*)(dsm + HX_SB);
    float* sb2 = (float*)(dsm + HX_SB2);

    int tid = threadIdx.x;
    int wid = tid >> 5, l = tid & 31;
    int gid = l >> 2, tig = l & 3;
    uint32_t* se = (uint32_t*)(dsm + HX_SE) + wid * 2176;

    for (int idx = tid; idx < 4096; idx += 256) {
        int k = idx >> 6, n = idx & 63;
        sw1[k * 72 + n] = f2tf32(w1a[k * 64 + n]);  // top rows 0..63
        sw2[k * 72 + n] = f2tf32(w2a[k * 64 + n]);
    }
    if (tid < 64) sb1[tid] = b1a[tid];
    else if (tid < 128) sb2[tid - 64] = b2a[tid - 64];
    __syncthreads();

    long long base = (long long)blockIdx.x * 256 + wid * 32;

#pragma unroll
    for (int i = 0; i < 16; i++) {
        int idx = l + 32 * i;
        int row = idx >> 4, k4 = (idx & 15) * 4;
        long long r = base + row;
        float4 v = (r < N) ? __ldg((const float4*)(x + r * 64 + k4))
                           : make_float4(0.f, 0.f, 0.f, 0.f);
        uint4 s;
        s.x = f2tf32(v.x); s.y = f2tf32(v.y); s.z = f2tf32(v.z); s.w = f2tf32(v.w);
        *(uint4*)(se + row * 68 + k4) = s;
    }
    __syncwarp();

    float c[2][8][4];
#pragma unroll 1
    for (int p = 0; p < 2; p++) {
        zero_c(c);
        warp_gemm(se, p ? sw2 : sw1, gid, tig, c);
        float* outg = p ? g_hx2 : g_hx;
        const float* sb = p ? sb2 : sb1;
#pragma unroll
        for (int mt = 0; mt < 2; mt++) {
            long long r0 = base + mt * 16 + gid;
#pragma unroll
            for (int j = 0; j < 8; j++) {
                float2 bb = *(const float2*)(sb + j * 8 + 2 * tig);
                if (r0 < N)
                    *(float2*)(outg + r0 * 64 + j * 8 + 2 * tig) =
                        make_float2(c[mt][j][0] + bb.x, c[mt][j][1] + bb.y);
                if (r0 + 8 < N)
                    *(float2*)(outg + (r0 + 8) * 64 + j * 8 + 2 * tig) =
                        make_float2(c[mt][j][2] + bb.x, c[mt][j][3] + bb.y);
            }
        }
    }
}

// ================= edge kernel: single GEMM + relu + row-major scatter-add =================
// h_e = relu(hx[src] + ea@w1a_bot); g_summed[dst] += h_e; count[dst]++
#define ED_SW1 0
#define ED_SE 18432
#define ED_SMEM (ED_SE + 8 * 32 * 68 * 4)  // 88064

__global__ void __launch_bounds__(256, 2) edge_mma_kernel(
    const int* __restrict__ ei, const float* __restrict__ ea,
    const float* __restrict__ w1a,  // rows 64..127 used
    int E, int ntiles) {
    extern __shared__ __align__(16) char dsm[];
    uint32_t* sw1 = (uint32_t*)(dsm + ED_SW1);

    int tid = threadIdx.x;
    int wid = tid >> 5, l = tid & 31;
    int gid = l >> 2, tig = l & 3;
    uint32_t* se = (uint32_t*)(dsm + ED_SE) + wid * 2176;
    float* sef = (float*)se;

    for (int idx = tid; idx < 4096; idx += 256) {
        int k = idx >> 6, n = idx & 63;
        sw1[k * 72 + n] = f2tf32(w1a[(64 + k) * 64 + n]);
    }
    __syncthreads();

    int half = l >> 4;   // 0..1 : which row of the pair
    int qc = l & 15;     // float4 chunk within a row

    for (int tile = blockIdx.x; tile < ntiles; tile += gridDim.x) {
        long long eb = (long long)tile * 256 + wid * 32;
        long long ee = eb + l;
        bool ev = (ee < E);
        int rsrc = ev ? ei[ee] : 0;
        int cdst = ev ? ei[E + ee] : 0;

        __syncwarp();
        // stage ea tile (32 edges x 64) tf32
#pragma unroll
        for (int i = 0; i < 16; i++) {
            int idx = l + 32 * i;
            int row = idx >> 4, k4 = (idx & 15) * 4;
            long long er = eb + row;
            float4 v = (er < E) ? __ldg((const float4*)(ea + er * 64 + k4))
                                : make_float4(0.f, 0.f, 0.f, 0.f);
            uint4 s;
            s.x = f2tf32(v.x); s.y = f2tf32(v.y); s.z = f2tf32(v.z); s.w = f2tf32(v.w);
            *(uint4*)(se + row * 68 + k4) = s;
        }
        __syncwarp();

        float c[2][8][4];
        zero_c(c);
        warp_gemm(se, sw1, gid, tig, c);
        __syncwarp();

        // transpose C into smem tile (fragment-layout stores)
#pragma unroll
        for (int mt = 0; mt < 2; mt++) {
            int r0 = mt * 16 + gid;
#pragma unroll
            for (int j = 0; j < 8; j++) {
                *(float2*)(sef + r0 * 68 + j * 8 + 2 * tig) =
                    make_float2(c[mt][j][0], c[mt][j][1]);
                *(float2*)(sef + (r0 + 8) * 68 + j * 8 + 2 * tig) =
                    make_float2(c[mt][j][2], c[mt][j][3]);
            }
        }
        __syncwarp();

        // row-major epilogue: 2 edge-rows per iteration, 16 lanes per row.
        // gather hx[src] coalesced (2 full 256B rows / instr), relu, red.v4 scatter.
#pragma unroll
        for (int i = 0; i < 16; i++) {
            int row = 2 * i + half;
            int src = __shfl_sync(0xffffffffu, rsrc, row);
            int dst = __shfl_sync(0xffffffffu, cdst, row);
            bool v = (eb + row) < E;
            float4 cv = *(const float4*)(sef + row * 68 + qc * 4);
            float4 hv = __ldg((const float4*)(g_hx + (size_t)src * DD + qc * 4));
            if (v) {
                float f0 = fmaxf(cv.x + hv.x, 0.f);
                float f1 = fmaxf(cv.y + hv.y, 0.f);
                float f2 = fmaxf(cv.z + hv.z, 0.f);
                float f3 = fmaxf(cv.w + hv.w, 0.f);
                asm volatile("red.global.add.v4.f32 [%0], {%1,%2,%3,%4};"
                             :: "l"(g_summed + (size_t)dst * DD + qc * 4),
                                "f"(f0), "f"(f1), "f"(f2), "f"(f3)
                             : "memory");
            }
        }
        if (ev) atomicAdd(&g_counts[cdst], 1.0f);
    }
}

// ================= node kernel: 3-stage chain =================
// hmean = g_summed[n]/max(cnt,1)
// agg   = hmean @ w1b + b1b*(cnt>0)
// h2    = relu(agg @ w2a_bot + hx2[n])
// out   = h2 @ w2b + b2b
#define ND_SW1 0
#define ND_SW2 18432
#define ND_SW3 36864
#define ND_SB1 55296
#define ND_SB2 55552
#define ND_SE 55808
#define ND_SMEM (ND_SE + 8 * 32 * 68 * 4)  // 125440

__global__ void __launch_bounds__(256, 1) node_mma_kernel(
    const float* __restrict__ w1b, const float* __restrict__ b1b,
    const float* __restrict__ w2a,  // rows 64..127 used
    const float* __restrict__ w2b, const float* __restrict__ b2b,
    float* __restrict__ out, int N) {
    extern __shared__ __align__(16) char dsm[];
    uint32_t* sw1 = (uint32_t*)(dsm + ND_SW1);
    uint32_t* sw2 = (uint32_t*)(dsm + ND_SW2);
    uint32_t* sw3 = (uint32_t*)(dsm + ND_SW3);
    float* sb1 = (float*)(dsm + ND_SB1);
    float* sb2 = (float*)(dsm + ND_SB2);

    int tid = threadIdx.x;
    int wid = tid >> 5, l = tid & 31;
    int gid = l >> 2, tig = l & 3;
    uint32_t* se = (uint32_t*)(dsm + ND_SE) + wid * 2176;

    for (int idx = tid; idx < 4096; idx += 256) {
        int k = idx >> 6, n = idx & 63;
        sw1[k * 72 + n] = f2tf32(w1b[k * 64 + n]);
        sw2[k * 72 + n] = f2tf32(w2a[(64 + k) * 64 + n]);
        sw3[k * 72 + n] = f2tf32(w2b[k * 64 + n]);
    }
    if (tid < 64) sb1[tid] = b1b[tid];
    else if (tid < 128) sb2[tid - 64] = b2b[tid - 64];
    __syncthreads();

    long long base = (long long)blockIdx.x * 256 + wid * 32;

    // stage hmean tile as tf32
#pragma unroll
    for (int i = 0; i < 16; i++) {
        int idx = l + 32 * i;
        int row = idx >> 4, k4 = (idx & 15) * 4;
        long long r = base + row;
        float4 v = make_float4(0.f, 0.f, 0.f, 0.f);
        if (r < N) {
            float inv = 1.0f / fmaxf(g_counts[r], 1.0f);
            float4 s = *(const float4*)(g_summed + r * 64 + k4);
            v = make_float4(s.x * inv, s.y * inv, s.z * inv, s.w * inv);
        }
        uint4 s;
        s.x = f2tf32(v.x); s.y = f2tf32(v.y); s.z = f2tf32(v.z); s.w = f2tf32(v.w);
        *(uint4*)(se + row * 68 + k4) = s;
    }
    __syncwarp();

    float c[2][8][4];

    // ---- stage 1: agg = hmean @ w1b^T + b1b*(cnt>0) ----
    zero_c(c);
    warp_gemm(se, sw1, gid, tig, c);
    __syncwarp();
#pragma unroll
    for (int mt = 0; mt < 2; mt++) {
        long long r0 = base + mt * 16 + gid;
        float flo = (r0 < N && g_counts[r0] > 0.f) ? 1.f : 0.f;
        float fhi = (r0 + 8 < N && g_counts[r0 + 8] > 0.f) ? 1.f : 0.f;
        int rr = mt * 16 + gid;
#pragma unroll
        for (int j = 0; j < 8; j++) {
            float2 bb = *(const float2*)(sb1 + j * 8 + 2 * tig);
            uint2 lo, hi;
            lo.x = f2tf32(c[mt][j][0] + flo * bb.x);
            lo.y = f2tf32(c[mt][j][1] + flo * bb.y);
            hi.x = f2tf32(c[mt][j][2] + fhi * bb.x);
            hi.y = f2tf32(c[mt][j][3] + fhi * bb.y);
            *(uint2*)(se + rr * 68 + j * 8 + 2 * tig) = lo;
            *(uint2*)(se + (rr + 8) * 68 + j * 8 + 2 * tig) = hi;
        }
    }
    __syncwarp();

    // ---- stage 2: h2 = relu(agg @ w2a_bot^T + hx2[n]) ----
    zero_c(c);
    warp_gemm(se, sw2, gid, tig, c);
    __syncwarp();
#pragma unroll
    for (int mt = 0; mt < 2; mt++) {
        long long r0 = base + mt * 16 + gid;
        long long rlo = (r0 < N) ? r0 : 0;
        long long rhi = (r0 + 8 < N) ? r0 + 8 : 0;
        const float* hlo = g_hx2 + rlo * DD + 2 * tig;
        const float* hhi = g_hx2 + rhi * DD + 2 * tig;
        int rr = mt * 16 + gid;
#pragma unroll
        for (int j = 0; j < 8; j++) {
            float2 xl = __ldg((const float2*)(hlo + j * 8));
            float2 xh = __ldg((const float2*)(hhi + j * 8));
            uint2 lo, hi;
            lo.x = f2tf32(fmaxf(c[mt][j][0] + xl.x, 0.f));
            lo.y = f2tf32(fmaxf(c[mt][j][1] + xl.y, 0.f));
            hi.x = f2tf32(fmaxf(c[mt][j][2] + xh.x, 0.f));
            hi.y = f2tf32(fmaxf(c[mt][j][3] + xh.y, 0.f));
            *(uint2*)(se + rr * 68 + j * 8 + 2 * tig) = lo;
            *(uint2*)(se + (rr + 8) * 68 + j * 8 + 2 * tig) = hi;
        }
    }
    __syncwarp();

    // ---- stage 3: out = h2 @ w2b^T + b2b ----
    zero_c(c);
    warp_gemm(se, sw3, gid, tig, c);
#pragma unroll
    for (int mt = 0; mt < 2; mt++) {
        long long r0 = base + mt * 16 + gid;
#pragma unroll
        for (int j = 0; j < 8; j++) {
            float2 bb = *(const float2*)(sb2 + j * 8 + 2 * tig);
            if (r0 < N)
                *(float2*)(out + r0 * 64 + j * 8 + 2 * tig) =
                    make_float2(c[mt][j][0] + bb.x, c[mt][j][1] + bb.y);
            if (r0 + 8 < N)
                *(float2*)(out + (r0 + 8) * 64 + j * 8 + 2 * tig) =
                    make_float2(c[mt][j][2] + bb.x, c[mt][j][3] + bb.y);
        }
    }
}

extern "C" void kernel_launch(void* const* d_in, const int* in_sizes, int n_in,
                              void* d_out, int out_size) {
    const float* x   = (const float*)d_in[0];
    const int*   ei  = (const int*)d_in[1];
    const float* ea  = (const float*)d_in[2];
    const float* w1a = (const float*)d_in[5];
    const float* b1a = (const float*)d_in[6];
    const float* w1b = (const float*)d_in[7];
    const float* b1b = (const float*)d_in[8];
    const float* w2a = (const float*)d_in[9];
    const float* b2a = (const float*)d_in[10];
    const float* w2b = (const float*)d_in[11];
    const float* b2b = (const float*)d_in[12];
    float* out = (float*)d_out;

    int N = in_sizes[0] / DD;
    int E = in_sizes[2] / DD;

    cudaFuncSetAttribute(hx_mma_kernel, cudaFuncAttributeMaxDynamicSharedMemorySize, HX_SMEM);
    cudaFuncSetAttribute(edge_mma_kernel, cudaFuncAttributeMaxDynamicSharedMemorySize, ED_SMEM);
    cudaFuncSetAttribute(node_mma_kernel, cudaFuncAttributeMaxDynamicSharedMemorySize, ND_SMEM);

    int ntiles_e = (E + 255) / 256;
    int grid_e = ntiles_e < 296 ? ntiles_e : 296;
    int ntiles_n = (N + 255) / 256;

    zero_summed<<<512, 256>>>(N * DD / 4);
    zero_counts<<<(N + 255) / 256, 256>>>(N);
    hx_mma_kernel<<<ntiles_n, 256, HX_SMEM>>>(x, w1a, b1a, w2a, b2a, N);
    edge_mma_kernel<<<grid_e, 256, ED_SMEM>>>(ei, ea, w1a, E, ntiles_e);
    node_mma_kernel<<<ntiles_n, 256, ND_SMEM>>>(w1b, b1b, w2a, w2b, b2b, out, N);
}

// round 14
// speedup vs baseline: 1.0072x; 1.0072x over previous
#include <cuda_runtime.h>
#include <cuda_bf16.h>
#include <cstdint>

#define MAX_N 50432
#define DD 64

__device__ __align__(16) float g_summed[MAX_N * DD];  // sum of relu(h_e) per dst node
__device__ float g_counts[MAX_N];
__device__ __align__(16) float g_hx[MAX_N * DD];   // x @ w1a[0:64] + b1a
__device__ __align__(16) float g_hx2[MAX_N * DD];  // x @ w2a[0:64] + b2a

// ---------- tf32 + mma helpers ----------
__device__ __forceinline__ uint32_t f2tf32(float f) {
    uint32_t r;
    asm("cvt.rna.tf32.f32 %0, %1;" : "=r"(r) : "f"(f));
    return r;
}
// D(16x8,f32) += A(16x8,tf32,row) * B(8x8,tf32,col)
__device__ __forceinline__ void mma_tf32(float* d, const uint32_t* a,
                                         uint32_t b0, uint32_t b1) {
    asm volatile(
        "mma.sync.aligned.m16n8k8.row.col.f32.tf32.tf32.f32 "
        "{%0,%1,%2,%3}, {%4,%5,%6,%7}, {%8,%9}, {%0,%1,%2,%3};"
        : "+f"(d[0]), "+f"(d[1]), "+f"(d[2]), "+f"(d[3])
        : "r"(a[0]), "r"(a[1]), "r"(a[2]), "r"(a[3]), "r"(b0), "r"(b1));
}

// Warp GEMM: C[32x64] += A(se: 32 rows x 64 k, stride 68) * B(sw: [k][n] stride 72)^T
__device__ __forceinline__ void warp_gemm(const uint32_t* se, const uint32_t* sw,
                                          int gid, int tig, float c[2][8][4]) {
#pragma unroll
    for (int kt = 0; kt < 8; kt++) {
        uint32_t a[2][4];
#pragma unroll
        for (int mt = 0; mt < 2; mt++) {
            int r0 = mt * 16 + gid;
            a[mt][0] = se[r0 * 68 + kt * 8 + tig];
            a[mt][1] = se[(r0 + 8) * 68 + kt * 8 + tig];
            a[mt][2] = se[r0 * 68 + kt * 8 + tig + 4];
            a[mt][3] = se[(r0 + 8) * 68 + kt * 8 + tig + 4];
        }
#pragma unroll
        for (int j = 0; j < 8; j++) {
            uint32_t b0 = sw[(kt * 8 + tig) * 72 + j * 8 + gid];
            uint32_t b1 = sw[(kt * 8 + tig + 4) * 72 + j * 8 + gid];
            mma_tf32(c[0][j], a[0], b0, b1);
            mma_tf32(c[1][j], a[1], b0, b1);
        }
    }
}

__device__ __forceinline__ void zero_c(float c[2][8][4]) {
#pragma unroll
    for (int mt = 0; mt < 2; mt++)
#pragma unroll
        for (int j = 0; j < 8; j++)
#pragma unroll
            for (int r = 0; r < 4; r++) c[mt][j][r] = 0.f;
}

// ---------- zero scratch ----------
__global__ void zero_summed(int n_f4) {
    int i = blockIdx.x * blockDim.x + threadIdx.x;
    int stride = gridDim.x * blockDim.x;
    float4 z = make_float4(0.f, 0.f, 0.f, 0.f);
    for (int j = i; j < n_f4; j += stride) ((float4*)g_summed)[j] = z;
}
__global__ void zero_counts(int n) {
    int i = blockIdx.x * blockDim.x + threadIdx.x;
    if (i < n) g_counts[i] = 0.f;
}

// ================= hx kernel: hx = x@w1a_top + b1a, hx2 = x@w2a_top + b2a =================
#define HX_SW1 0
#define HX_SW2 18432
#define HX_SB 36864
#define HX_SB2 37120
#define HX_SE 37376
#define HX_SMEM (HX_SE + 8 * 32 * 68 * 4)  // 107008

__global__ void __launch_bounds__(256, 2) hx_mma_kernel(
    const float* __restrict__ x,
    const float* __restrict__ w1a, const float* __restrict__ b1a,
    const float* __restrict__ w2a, const float* __restrict__ b2a,
    int N) {
    extern __shared__ __align__(16) char dsm[];
    uint32_t* sw1 = (uint32_t*)(dsm + HX_SW1);
    uint32_t* sw2 = (uint32_t*)(dsm + HX_SW2);
    float* sb1 = (float*)(dsm + HX_SB);
    float* sb2 = (float*)(dsm + HX_SB2);

    int tid = threadIdx.x;
    int wid = tid >> 5, l = tid & 31;
    int gid = l >> 2, tig = l & 3;
    uint32_t* se = (uint32_t*)(dsm + HX_SE) + wid * 2176;

    for (int idx = tid; idx < 4096; idx += 256) {
        int k = idx >> 6, n = idx & 63;
        sw1[k * 72 + n] = f2tf32(w1a[k * 64 + n]);  // top rows 0..63
        sw2[k * 72 + n] = f2tf32(w2a[k * 64 + n]);
    }
    if (tid < 64) sb1[tid] = b1a[tid];
    else if (tid < 128) sb2[tid - 64] = b2a[tid - 64];
    __syncthreads();

    long long base = (long long)blockIdx.x * 256 + wid * 32;

#pragma unroll
    for (int i = 0; i < 16; i++) {
        int idx = l + 32 * i;
        int row = idx >> 4, k4 = (idx & 15) * 4;
        long long r = base + row;
        float4 v = (r < N) ? __ldg((const float4*)(x + r * 64 + k4))
                           : make_float4(0.f, 0.f, 0.f, 0.f);
        uint4 s;
        s.x = f2tf32(v.x); s.y = f2tf32(v.y); s.z = f2tf32(v.z); s.w = f2tf32(v.w);
        *(uint4*)(se + row * 68 + k4) = s;
    }
    __syncwarp();

    float c[2][8][4];
#pragma unroll 1
    for (int p = 0; p < 2; p++) {
        zero_c(c);
        warp_gemm(se, p ? sw2 : sw1, gid, tig, c);
        float* outg = p ? g_hx2 : g_hx;
        const float* sb = p ? sb2 : sb1;
#pragma unroll
        for (int mt = 0; mt < 2; mt++) {
            long long r0 = base + mt * 16 + gid;
#pragma unroll
            for (int j = 0; j < 8; j++) {
                float2 bb = *(const float2*)(sb + j * 8 + 2 * tig);
                if (r0 < N)
                    *(float2*)(outg + r0 * 64 + j * 8 + 2 * tig) =
                        make_float2(c[mt][j][0] + bb.x, c[mt][j][1] + bb.y);
                if (r0 + 8 < N)
                    *(float2*)(outg + (r0 + 8) * 64 + j * 8 + 2 * tig) =
                        make_float2(c[mt][j][2] + bb.x, c[mt][j][3] + bb.y);
            }
        }
    }
}

// ================= edge kernel: single GEMM + relu + row-major scatter-add =================
// h_e = relu(hx[src] + ea@w1a_bot); g_summed[dst] += h_e; count[dst]++
#define ED_SW1 0
#define ED_SE 18432
#define ED_SMEM (ED_SE + 8 * 32 * 68 * 4)  // 88064

__global__ void __launch_bounds__(256, 2) edge_mma_kernel(
    const int* __restrict__ ei, const float* __restrict__ ea,
    const float* __restrict__ w1a,  // rows 64..127 used
    int E, int ntiles) {
    extern __shared__ __align__(16) char dsm[];
    uint32_t* sw1 = (uint32_t*)(dsm + ED_SW1);

    int tid = threadIdx.x;
    int wid = tid >> 5, l = tid & 31;
    int gid = l >> 2, tig = l & 3;
    uint32_t* se = (uint32_t*)(dsm + ED_SE) + wid * 2176;
    float* sef = (float*)se;

    for (int idx = tid; idx < 4096; idx += 256) {
        int k = idx >> 6, n = idx & 63;
        sw1[k * 72 + n] = f2tf32(w1a[(64 + k) * 64 + n]);
    }
    __syncthreads();

    int half = l >> 4;   // 0..1 : which row of the pair
    int qc = l & 15;     // float4 chunk within a row

    for (int tile = blockIdx.x; tile < ntiles; tile += gridDim.x) {
        long long eb = (long long)tile * 256 + wid * 32;
        long long ee = eb + l;
        bool ev = (ee < E);
        int rsrc = ev ? ei[ee] : 0;
        int cdst = ev ? ei[E + ee] : 0;

        __syncwarp();
        // stage ea tile (32 edges x 64) tf32
#pragma unroll
        for (int i = 0; i < 16; i++) {
            int idx = l + 32 * i;
            int row = idx >> 4, k4 = (idx & 15) * 4;
            long long er = eb + row;
            float4 v = (er < E) ? __ldg((const float4*)(ea + er * 64 + k4))
                                : make_float4(0.f, 0.f, 0.f, 0.f);
            uint4 s;
            s.x = f2tf32(v.x); s.y = f2tf32(v.y); s.z = f2tf32(v.z); s.w = f2tf32(v.w);
            *(uint4*)(se + row * 68 + k4) = s;
        }
        __syncwarp();

        float c[2][8][4];
        zero_c(c);
        warp_gemm(se, sw1, gid, tig, c);
        __syncwarp();

        // transpose C into smem tile (fragment-layout stores)
#pragma unroll
        for (int mt = 0; mt < 2; mt++) {
            int r0 = mt * 16 + gid;
#pragma unroll
            for (int j = 0; j < 8; j++) {
                *(float2*)(sef + r0 * 68 + j * 8 + 2 * tig) =
                    make_float2(c[mt][j][0], c[mt][j][1]);
                *(float2*)(sef + (r0 + 8) * 68 + j * 8 + 2 * tig) =
                    make_float2(c[mt][j][2], c[mt][j][3]);
            }
        }
        __syncwarp();

        // row-major epilogue: 2 edge-rows per iteration, 16 lanes per row.
        // gather hx[src] coalesced (2 full 256B rows / instr), relu, red.v4 scatter.
#pragma unroll
        for (int i = 0; i < 16; i++) {
            int row = 2 * i + half;
            int src = __shfl_sync(0xffffffffu, rsrc, row);
            int dst = __shfl_sync(0xffffffffu, cdst, row);
            bool v = (eb + row) < E;
            float4 cv = *(const float4*)(sef + row * 68 + qc * 4);
            float4 hv = __ldg((const float4*)(g_hx + (size_t)src * DD + qc * 4));
            if (v) {
                float f0 = fmaxf(cv.x + hv.x, 0.f);
                float f1 = fmaxf(cv.y + hv.y, 0.f);
                float f2 = fmaxf(cv.z + hv.z, 0.f);
                float f3 = fmaxf(cv.w + hv.w, 0.f);
                asm volatile("red.global.add.v4.f32 [%0], {%1,%2,%3,%4};"
                             :: "l"(g_summed + (size_t)dst * DD + qc * 4),
                                "f"(f0), "f"(f1), "f"(f2), "f"(f3)
                             : "memory");
            }
        }
        if (ev) atomicAdd(&g_counts[cdst], 1.0f);
    }
}

// ================= node kernel: 3-stage chain =================
// hmean = g_summed[n]/max(cnt,1)
// agg   = hmean @ w1b + b1b*(cnt>0)
// h2    = relu(agg @ w2a_bot + hx2[n])
// out   = h2 @ w2b + b2b
#define ND_SW1 0
#define ND_SW2 18432
#define ND_SW3 36864
#define ND_SB1 55296
#define ND_SB2 55552
#define ND_SE 55808
#define ND_SMEM (ND_SE + 8 * 32 * 68 * 4)  // 125440

__global__ void __launch_bounds__(256, 1) node_mma_kernel(
    const float* __restrict__ w1b, const float* __restrict__ b1b,
    const float* __restrict__ w2a,  // rows 64..127 used
    const float* __restrict__ w2b, const float* __restrict__ b2b,
    float* __restrict__ out, int N) {
    extern __shared__ __align__(16) char dsm[];
    uint32_t* sw1 = (uint32_t*)(dsm + ND_SW1);
    uint32_t* sw2 = (uint32_t*)(dsm + ND_SW2);
    uint32_t* sw3 = (uint32_t*)(dsm + ND_SW3);
    float* sb1 = (float*)(dsm + ND_SB1);
    float* sb2 = (float*)(dsm + ND_SB2);

    int tid = threadIdx.x;
    int wid = tid >> 5, l = tid & 31;
    int gid = l >> 2, tig = l & 3;
    uint32_t* se = (uint32_t*)(dsm + ND_SE) + wid * 2176;

    for (int idx = tid; idx < 4096; idx += 256) {
        int k = idx >> 6, n = idx & 63;
        sw1[k * 72 + n] = f2tf32(w1b[k * 64 + n]);
        sw2[k * 72 + n] = f2tf32(w2a[(64 + k) * 64 + n]);
        sw3[k * 72 + n] = f2tf32(w2b[k * 64 + n]);
    }
    if (tid < 64) sb1[tid] = b1b[tid];
    else if (tid < 128) sb2[tid - 64] = b2b[tid - 64];
    __syncthreads();

    long long base = (long long)blockIdx.x * 256 + wid * 32;

    // stage hmean tile as tf32
#pragma unroll
    for (int i = 0; i < 16; i++) {
        int idx = l + 32 * i;
        int row = idx >> 4, k4 = (idx & 15) * 4;
        long long r = base + row;
        float4 v = make_float4(0.f, 0.f, 0.f, 0.f);
        if (r < N) {
            float inv = 1.0f / fmaxf(g_counts[r], 1.0f);
            float4 s = *(const float4*)(g_summed + r * 64 + k4);
            v = make_float4(s.x * inv, s.y * inv, s.z * inv, s.w * inv);
        }
        uint4 s;
        s.x = f2tf32(v.x); s.y = f2tf32(v.y); s.z = f2tf32(v.z); s.w = f2tf32(v.w);
        *(uint4*)(se + row * 68 + k4) = s;
    }
    __syncwarp();

    float c[2][8][4];

    // ---- stage 1: agg = hmean @ w1b^T + b1b*(cnt>0) ----
    zero_c(c);
    warp_gemm(se, sw1, gid, tig, c);
    __syncwarp();
#pragma unroll
    for (int mt = 0; mt < 2; mt++) {
        long long r0 = base + mt * 16 + gid;
        float flo = (r0 < N && g_counts[r0] > 0.f) ? 1.f : 0.f;
        float fhi = (r0 + 8 < N && g_counts[r0 + 8] > 0.f) ? 1.f : 0.f;
        int rr = mt * 16 + gid;
#pragma unroll
        for (int j = 0; j < 8; j++) {
            float2 bb = *(const float2*)(sb1 + j * 8 + 2 * tig);
            uint2 lo, hi;
            lo.x = f2tf32(c[mt][j][0] + flo * bb.x);
            lo.y = f2tf32(c[mt][j][1] + flo * bb.y);
            hi.x = f2tf32(c[mt][j][2] + fhi * bb.x);
            hi.y = f2tf32(c[mt][j][3] + fhi * bb.y);
            *(uint2*)(se + rr * 68 + j * 8 + 2 * tig) = lo;
            *(uint2*)(se + (rr + 8) * 68 + j * 8 + 2 * tig) = hi;
        }
    }
    __syncwarp();

    // ---- stage 2: h2 = relu(agg @ w2a_bot^T + hx2[n]) ----
    zero_c(c);
    warp_gemm(se, sw2, gid, tig, c);
    __syncwarp();
#pragma unroll
    for (int mt = 0; mt < 2; mt++) {
        long long r0 = base + mt * 16 + gid;
        long long rlo = (r0 < N) ? r0 : 0;
        long long rhi = (r0 + 8 < N) ? r0 + 8 : 0;
        const float* hlo = g_hx2 + rlo * DD + 2 * tig;
        const float* hhi = g_hx2 + rhi * DD + 2 * tig;
        int rr = mt * 16 + gid;
#pragma unroll
        for (int j = 0; j < 8; j++) {
            float2 xl = __ldg((const float2*)(hlo + j * 8));
            float2 xh = __ldg((const float2*)(hhi + j * 8));
            uint2 lo, hi;
            lo.x = f2tf32(fmaxf(c[mt][j][0] + xl.x, 0.f));
            lo.y = f2tf32(fmaxf(c[mt][j][1] + xl.y, 0.f));
            hi.x = f2tf32(fmaxf(c[mt][j][2] + xh.x, 0.f));
            hi.y = f2tf32(fmaxf(c[mt][j][3] + xh.y, 0.f));
            *(uint2*)(se + rr * 68 + j * 8 + 2 * tig) = lo;
            *(uint2*)(se + (rr + 8) * 68 + j * 8 + 2 * tig) = hi;
        }
    }
    __syncwarp();

    // ---- stage 3: out = h2 @ w2b^T + b2b ----
    zero_c(c);
    warp_gemm(se, sw3, gid, tig, c);
#pragma unroll
    for (int mt = 0; mt < 2; mt++) {
        long long r0 = base + mt * 16 + gid;
#pragma unroll
        for (int j = 0; j < 8; j++) {
            float2 bb = *(const float2*)(sb2 + j * 8 + 2 * tig);
            if (r0 < N)
                *(float2*)(out + r0 * 64 + j * 8 + 2 * tig) =
                    make_float2(c[mt][j][0] + bb.x, c[mt][j][1] + bb.y);
            if (r0 + 8 < N)
                *(float2*)(out + (r0 + 8) * 64 + j * 8 + 2 * tig) =
                    make_float2(c[mt][j][2] + bb.x, c[mt][j][3] + bb.y);
        }
    }
}

extern "C" void kernel_launch(void* const* d_in, const int* in_sizes, int n_in,
                              void* d_out, int out_size) {
    const float* x   = (const float*)d_in[0];
    const int*   ei  = (const int*)d_in[1];
    const float* ea  = (const float*)d_in[2];
    const float* w1a = (const float*)d_in[5];
    const float* b1a = (const float*)d_in[6];
    const float* w1b = (const float*)d_in[7];
    const float* b1b = (const float*)d_in[8];
    const float* w2a = (const float*)d_in[9];
    const float* b2a = (const float*)d_in[10];
    const float* w2b = (const float*)d_in[11];
    const float* b2b = (const float*)d_in[12];
    float* out = (float*)d_out;

    int N = in_sizes[0] / DD;
    int E = in_sizes[2] / DD;

    cudaFuncSetAttribute(hx_mma_kernel, cudaFuncAttributeMaxDynamicSharedMemorySize, HX_SMEM);
    cudaFuncSetAttribute(edge_mma_kernel, cudaFuncAttributeMaxDynamicSharedMemorySize, ED_SMEM);
    cudaFuncSetAttribute(node_mma_kernel, cudaFuncAttributeMaxDynamicSharedMemorySize, ND_SMEM);

    int ntiles_e = (E + 255) / 256;
    int grid_e = ntiles_e < 296 ? ntiles_e : 296;
    int ntiles_n = (N + 255) / 256;

    zero_summed<<<512, 256>>>(N * DD / 4);
    zero_counts<<<(N + 255) / 256, 256>>>(N);
    hx_mma_kernel<<<ntiles_n, 256, HX_SMEM>>>(x, w1a, b1a, w2a, b2a, N);
    edge_mma_kernel<<<grid_e, 256, ED_SMEM>>>(ei, ea, w1a, E, ntiles_e);
    node_mma_kernel<<<ntiles_n, 256, ND_SMEM>>>(w1b, b1b, w2a, w2b, b2b, out, N);
}

// round 15
// speedup vs baseline: 1.0095x; 1.0022x over previous
#include <cuda_runtime.h>
#include <cuda_bf16.h>
#include <cstdint>

#define MAX_N 50432
#define DD 64

__device__ __align__(16) float g_summed[MAX_N * DD];  // sum of relu(h_e) per dst node
__device__ float g_counts[MAX_N];
__device__ __align__(16) float g_hx[MAX_N * DD];   // x @ w1a[0:64] + b1a
__device__ __align__(16) float g_hx2[MAX_N * DD];  // x @ w2a[0:64] + b2a

// ---------- tf32 + mma helpers ----------
__device__ __forceinline__ uint32_t f2tf32(float f) {
    uint32_t r;
    asm("cvt.rna.tf32.f32 %0, %1;" : "=r"(r) : "f"(f));
    return r;
}
// D(16x8,f32) += A(16x8,tf32,row) * B(8x8,tf32,col)
__device__ __forceinline__ void mma_tf32(float* d, const uint32_t* a,
                                         uint32_t b0, uint32_t b1) {
    asm volatile(
        "mma.sync.aligned.m16n8k8.row.col.f32.tf32.tf32.f32 "
        "{%0,%1,%2,%3}, {%4,%5,%6,%7}, {%8,%9}, {%0,%1,%2,%3};"
        : "+f"(d[0]), "+f"(d[1]), "+f"(d[2]), "+f"(d[3])
        : "r"(a[0]), "r"(a[1]), "r"(a[2]), "r"(a[3]), "r"(b0), "r"(b1));
}

// Warp GEMM: C[32x64] += A(se: 32 rows x 64 k, stride 68) * B(sw: [k][n] stride 72)^T
__device__ __forceinline__ void warp_gemm(const uint32_t* se, const uint32_t* sw,
                                          int gid, int tig, float c[2][8][4]) {
#pragma unroll
    for (int kt = 0; kt < 8; kt++) {
        uint32_t a[2][4];
#pragma unroll
        for (int mt = 0; mt < 2; mt++) {
            int r0 = mt * 16 + gid;
            a[mt][0] = se[r0 * 68 + kt * 8 + tig];
            a[mt][1] = se[(r0 + 8) * 68 + kt * 8 + tig];
            a[mt][2] = se[r0 * 68 + kt * 8 + tig + 4];
            a[mt][3] = se[(r0 + 8) * 68 + kt * 8 + tig + 4];
        }
#pragma unroll
        for (int j = 0; j < 8; j++) {
            uint32_t b0 = sw[(kt * 8 + tig) * 72 + j * 8 + gid];
            uint32_t b1 = sw[(kt * 8 + tig + 4) * 72 + j * 8 + gid];
            mma_tf32(c[0][j], a[0], b0, b1);
            mma_tf32(c[1][j], a[1], b0, b1);
        }
    }
}

__device__ __forceinline__ void zero_c(float c[2][8][4]) {
#pragma unroll
    for (int mt = 0; mt < 2; mt++)
#pragma unroll
        for (int j = 0; j < 8; j++)
#pragma unroll
            for (int r = 0; r < 4; r++) c[mt][j][r] = 0.f;
}

// ---------- zero scratch ----------
__global__ void zero_summed(int n_f4) {
    int i = blockIdx.x * blockDim.x + threadIdx.x;
    int stride = gridDim.x * blockDim.x;
    float4 z = make_float4(0.f, 0.f, 0.f, 0.f);
    for (int j = i; j < n_f4; j += stride) ((float4*)g_summed)[j] = z;
}
__global__ void zero_counts(int n) {
    int i = blockIdx.x * blockDim.x + threadIdx.x;
    if (i < n) g_counts[i] = 0.f;
}

// ================= hx kernel: hx = x@w1a_top + b1a, hx2 = x@w2a_top + b2a =================
#define HX_SW1 0
#define HX_SW2 18432
#define HX_SB 36864
#define HX_SB2 37120
#define HX_SE 37376
#define HX_SMEM (HX_SE + 8 * 32 * 68 * 4)  // 107008

__global__ void __launch_bounds__(256, 2) hx_mma_kernel(
    const float* __restrict__ x,
    const float* __restrict__ w1a, const float* __restrict__ b1a,
    const float* __restrict__ w2a, const float* __restrict__ b2a,
    int N) {
    extern __shared__ __align__(16) char dsm[];
    uint32_t* sw1 = (uint32_t*)(dsm + HX_SW1);
    uint32_t* sw2 = (uint32_t*)(dsm + HX_SW2);
    float* sb1 = (float*)(dsm + HX_SB);
    float* sb2 = (float*)(dsm + HX_SB2);

    int tid = threadIdx.x;
    int wid = tid >> 5, l = tid & 31;
    int gid = l >> 2, tig = l & 3;
    uint32_t* se = (uint32_t*)(dsm + HX_SE) + wid * 2176;

    for (int idx = tid; idx < 4096; idx += 256) {
        int k = idx >> 6, n = idx & 63;
        sw1[k * 72 + n] = f2tf32(w1a[k * 64 + n]);  // top rows 0..63
        sw2[k * 72 + n] = f2tf32(w2a[k * 64 + n]);
    }
    if (tid < 64) sb1[tid] = b1a[tid];
    else if (tid < 128) sb2[tid - 64] = b2a[tid - 64];
    __syncthreads();

    long long base = (long long)blockIdx.x * 256 + wid * 32;

#pragma unroll
    for (int i = 0; i < 16; i++) {
        int idx = l + 32 * i;
        int row = idx >> 4, k4 = (idx & 15) * 4;
        long long r = base + row;
        float4 v = (r < N) ? __ldg((const float4*)(x + r * 64 + k4))
                           : make_float4(0.f, 0.f, 0.f, 0.f);
        uint4 s;
        s.x = f2tf32(v.x); s.y = f2tf32(v.y); s.z = f2tf32(v.z); s.w = f2tf32(v.w);
        *(uint4*)(se + row * 68 + k4) = s;
    }
    __syncwarp();

    float c[2][8][4];
#pragma unroll 1
    for (int p = 0; p < 2; p++) {
        zero_c(c);
        warp_gemm(se, p ? sw2 : sw1, gid, tig, c);
        float* outg = p ? g_hx2 : g_hx;
        const float* sb = p ? sb2 : sb1;
#pragma unroll
        for (int mt = 0; mt < 2; mt++) {
            long long r0 = base + mt * 16 + gid;
#pragma unroll
            for (int j = 0; j < 8; j++) {
                float2 bb = *(const float2*)(sb + j * 8 + 2 * tig);
                if (r0 < N)
                    *(float2*)(outg + r0 * 64 + j * 8 + 2 * tig) =
                        make_float2(c[mt][j][0] + bb.x, c[mt][j][1] + bb.y);
                if (r0 + 8 < N)
                    *(float2*)(outg + (r0 + 8) * 64 + j * 8 + 2 * tig) =
                        make_float2(c[mt][j][2] + bb.x, c[mt][j][3] + bb.y);
            }
        }
    }
}

// ================= edge kernel: single GEMM + relu + row-major scatter-add =================
// h_e = relu(hx[src] + ea@w1a_bot); g_summed[dst] += h_e; count[dst]++
#define ED_SW1 0
#define ED_SE 18432
#define ED_SMEM (ED_SE + 8 * 32 * 68 * 4)  // 88064

__global__ void __launch_bounds__(256, 2) edge_mma_kernel(
    const int* __restrict__ ei, const float* __restrict__ ea,
    const float* __restrict__ w1a,  // rows 64..127 used
    int E, int ntiles) {
    extern __shared__ __align__(16) char dsm[];
    uint32_t* sw1 = (uint32_t*)(dsm + ED_SW1);

    int tid = threadIdx.x;
    int wid = tid >> 5, l = tid & 31;
    int gid = l >> 2, tig = l & 3;
    uint32_t* se = (uint32_t*)(dsm + ED_SE) + wid * 2176;
    float* sef = (float*)se;

    for (int idx = tid; idx < 4096; idx += 256) {
        int k = idx >> 6, n = idx & 63;
        sw1[k * 72 + n] = f2tf32(w1a[(64 + k) * 64 + n]);
    }
    __syncthreads();

    int half = l >> 4;   // 0..1 : which row of the pair
    int qc = l & 15;     // float4 chunk within a row

    for (int tile = blockIdx.x; tile < ntiles; tile += gridDim.x) {
        long long eb = (long long)tile * 256 + wid * 32;
        long long ee = eb + l;
        bool ev = (ee < E);
        int rsrc = ev ? ei[ee] : 0;
        int cdst = ev ? ei[E + ee] : 0;

        __syncwarp();
        // stage ea tile (32 edges x 64) tf32
#pragma unroll
        for (int i = 0; i < 16; i++) {
            int idx = l + 32 * i;
            int row = idx >> 4, k4 = (idx & 15) * 4;
            long long er = eb + row;
            float4 v = (er < E) ? __ldg((const float4*)(ea + er * 64 + k4))
                                : make_float4(0.f, 0.f, 0.f, 0.f);
            uint4 s;
            s.x = f2tf32(v.x); s.y = f2tf32(v.y); s.z = f2tf32(v.z); s.w = f2tf32(v.w);
            *(uint4*)(se + row * 68 + k4) = s;
        }
        __syncwarp();

        float c[2][8][4];
        zero_c(c);
        warp_gemm(se, sw1, gid, tig, c);
        __syncwarp();

        // transpose C into smem tile (fragment-layout stores)
#pragma unroll
        for (int mt = 0; mt < 2; mt++) {
            int r0 = mt * 16 + gid;
#pragma unroll
            for (int j = 0; j < 8; j++) {
                *(float2*)(sef + r0 * 68 + j * 8 + 2 * tig) =
                    make_float2(c[mt][j][0], c[mt][j][1]);
                *(float2*)(sef + (r0 + 8) * 68 + j * 8 + 2 * tig) =
                    make_float2(c[mt][j][2], c[mt][j][3]);
            }
        }
        __syncwarp();

        // row-major epilogue: 2 edge-rows per iteration, 16 lanes per row.
        // gather hx[src] coalesced (2 full 256B rows / instr), relu, red.v4 scatter.
#pragma unroll
        for (int i = 0; i < 16; i++) {
            int row = 2 * i + half;
            int src = __shfl_sync(0xffffffffu, rsrc, row);
            int dst = __shfl_sync(0xffffffffu, cdst, row);
            bool v = (eb + row) < E;
            float4 cv = *(const float4*)(sef + row * 68 + qc * 4);
            float4 hv = __ldg((const float4*)(g_hx + (size_t)src * DD + qc * 4));
            if (v) {
                float f0 = fmaxf(cv.x + hv.x, 0.f);
                float f1 = fmaxf(cv.y + hv.y, 0.f);
                float f2 = fmaxf(cv.z + hv.z, 0.f);
                float f3 = fmaxf(cv.w + hv.w, 0.f);
                asm volatile("red.global.add.v4.f32 [%0], {%1,%2,%3,%4};"
                             :: "l"(g_summed + (size_t)dst * DD + qc * 4),
                                "f"(f0), "f"(f1), "f"(f2), "f"(f3)
                             : "memory");
            }
        }
        if (ev) atomicAdd(&g_counts[cdst], 1.0f);
    }
}

// ================= node kernel: 3-stage chain =================
// hmean = g_summed[n]/max(cnt,1)
// agg   = hmean @ w1b + b1b*(cnt>0)
// h2    = relu(agg @ w2a_bot + hx2[n])
// out   = h2 @ w2b + b2b
#define ND_SW1 0
#define ND_SW2 18432
#define ND_SW3 36864
#define ND_SB1 55296
#define ND_SB2 55552
#define ND_SE 55808
#define ND_SMEM (ND_SE + 8 * 32 * 68 * 4)  // 125440

__global__ void __launch_bounds__(256, 1) node_mma_kernel(
    const float* __restrict__ w1b, const float* __restrict__ b1b,
    const float* __restrict__ w2a,  // rows 64..127 used
    const float* __restrict__ w2b, const float* __restrict__ b2b,
    float* __restrict__ out, int N) {
    extern __shared__ __align__(16) char dsm[];
    uint32_t* sw1 = (uint32_t*)(dsm + ND_SW1);
    uint32_t* sw2 = (uint32_t*)(dsm + ND_SW2);
    uint32_t* sw3 = (uint32_t*)(dsm + ND_SW3);
    float* sb1 = (float*)(dsm + ND_SB1);
    float* sb2 = (float*)(dsm + ND_SB2);

    int tid = threadIdx.x;
    int wid = tid >> 5, l = tid & 31;
    int gid = l >> 2, tig = l & 3;
    uint32_t* se = (uint32_t*)(dsm + ND_SE) + wid * 2176;

    for (int idx = tid; idx < 4096; idx += 256) {
        int k = idx >> 6, n = idx & 63;
        sw1[k * 72 + n] = f2tf32(w1b[k * 64 + n]);
        sw2[k * 72 + n] = f2tf32(w2a[(64 + k) * 64 + n]);
        sw3[k * 72 + n] = f2tf32(w2b[k * 64 + n]);
    }
    if (tid < 64) sb1[tid] = b1b[tid];
    else if (tid < 128) sb2[tid - 64] = b2b[tid - 64];
    __syncthreads();

    long long base = (long long)blockIdx.x * 256 + wid * 32;

    // stage hmean tile as tf32
#pragma unroll
    for (int i = 0; i < 16; i++) {
        int idx = l + 32 * i;
        int row = idx >> 4, k4 = (idx & 15) * 4;
        long long r = base + row;
        float4 v = make_float4(0.f, 0.f, 0.f, 0.f);
        if (r < N) {
            float inv = 1.0f / fmaxf(g_counts[r], 1.0f);
            float4 s = *(const float4*)(g_summed + r * 64 + k4);
            v = make_float4(s.x * inv, s.y * inv, s.z * inv, s.w * inv);
        }
        uint4 s;
        s.x = f2tf32(v.x); s.y = f2tf32(v.y); s.z = f2tf32(v.z); s.w = f2tf32(v.w);
        *(uint4*)(se + row * 68 + k4) = s;
    }
    __syncwarp();

    float c[2][8][4];

    // ---- stage 1: agg = hmean @ w1b^T + b1b*(cnt>0) ----
    zero_c(c);
    warp_gemm(se, sw1, gid, tig, c);
    __syncwarp();
#pragma unroll
    for (int mt = 0; mt < 2; mt++) {
        long long r0 = base + mt * 16 + gid;
        float flo = (r0 < N && g_counts[r0] > 0.f) ? 1.f : 0.f;
        float fhi = (r0 + 8 < N && g_counts[r0 + 8] > 0.f) ? 1.f : 0.f;
        int rr = mt * 16 + gid;
#pragma unroll
        for (int j = 0; j < 8; j++) {
            float2 bb = *(const float2*)(sb1 + j * 8 + 2 * tig);
            uint2 lo, hi;
            lo.x = f2tf32(c[mt][j][0] + flo * bb.x);
            lo.y = f2tf32(c[mt][j][1] + flo * bb.y);
            hi.x = f2tf32(c[mt][j][2] + fhi * bb.x);
            hi.y = f2tf32(c[mt][j][3] + fhi * bb.y);
            *(uint2*)(se + rr * 68 + j * 8 + 2 * tig) = lo;
            *(uint2*)(se + (rr + 8) * 68 + j * 8 + 2 * tig) = hi;
        }
    }
    __syncwarp();

    // ---- stage 2: h2 = relu(agg @ w2a_bot^T + hx2[n]) ----
    zero_c(c);
    warp_gemm(se, sw2, gid, tig, c);
    __syncwarp();
#pragma unroll
    for (int mt = 0; mt < 2; mt++) {
        long long r0 = base + mt * 16 + gid;
        long long rlo = (r0 < N) ? r0 : 0;
        long long rhi = (r0 + 8 < N) ? r0 + 8 : 0;
        const float* hlo = g_hx2 + rlo * DD + 2 * tig;
        const float* hhi = g_hx2 + rhi * DD + 2 * tig;
        int rr = mt * 16 + gid;
#pragma unroll
        for (int j = 0; j < 8; j++) {
            float2 xl = __ldg((const float2*)(hlo + j * 8));
            float2 xh = __ldg((const float2*)(hhi + j * 8));
            uint2 lo, hi;
            lo.x = f2tf32(fmaxf(c[mt][j][0] + xl.x, 0.f));
            lo.y = f2tf32(fmaxf(c[mt][j][1] + xl.y, 0.f));
            hi.x = f2tf32(fmaxf(c[mt][j][2] + xh.x, 0.f));
            hi.y = f2tf32(fmaxf(c[mt][j][3] + xh.y, 0.f));
            *(uint2*)(se + rr * 68 + j * 8 + 2 * tig) = lo;
            *(uint2*)(se + (rr + 8) * 68 + j * 8 + 2 * tig) = hi;
        }
    }
    __syncwarp();

    // ---- stage 3: out = h2 @ w2b^T + b2b ----
    zero_c(c);
    warp_gemm(se, sw3, gid, tig, c);
#pragma unroll
    for (int mt = 0; mt < 2; mt++) {
        long long r0 = base + mt * 16 + gid;
#pragma unroll
        for (int j = 0; j < 8; j++) {
            float2 bb = *(const float2*)(sb2 + j * 8 + 2 * tig);
            if (r0 < N)
                *(float2*)(out + r0 * 64 + j * 8 + 2 * tig) =
                    make_float2(c[mt][j][0] + bb.x, c[mt][j][1] + bb.y);
            if (r0 + 8 < N)
                *(float2*)(out + (r0 + 8) * 64 + j * 8 + 2 * tig) =
                    make_float2(c[mt][j][2] + bb.x, c[mt][j][3] + bb.y);
        }
    }
}

extern "C" void kernel_launch(void* const* d_in, const int* in_sizes, int n_in,
                              void* d_out, int out_size) {
    const float* x   = (const float*)d_in[0];
    const int*   ei  = (const int*)d_in[1];
    const float* ea  = (const float*)d_in[2];
    const float* w1a = (const float*)d_in[5];
    const float* b1a = (const float*)d_in[6];
    const float* w1b = (const float*)d_in[7];
    const float* b1b = (const float*)d_in[8];
    const float* w2a = (const float*)d_in[9];
    const float* b2a = (const float*)d_in[10];
    const float* w2b = (const float*)d_in[11];
    const float* b2b = (const float*)d_in[12];
    float* out = (float*)d_out;

    int N = in_sizes[0] / DD;
    int E = in_sizes[2] / DD;

    cudaFuncSetAttribute(hx_mma_kernel, cudaFuncAttributeMaxDynamicSharedMemorySize, HX_SMEM);
    cudaFuncSetAttribute(edge_mma_kernel, cudaFuncAttributeMaxDynamicSharedMemorySize, ED_SMEM);
    cudaFuncSetAttribute(node_mma_kernel, cudaFuncAttributeMaxDynamicSharedMemorySize, ND_SMEM);

    int ntiles_e = (E + 255) / 256;
    int grid_e = ntiles_e < 296 ? ntiles_e : 296;
    int ntiles_n = (N + 255) / 256;

    zero_summed<<<512, 256>>>(N * DD / 4);
    zero_counts<<<(N + 255) / 256, 256>>>(N);
    hx_mma_kernel<<<ntiles_n, 256, HX_SMEM>>>(x, w1a, b1a, w2a, b2a, N);
    edge_mma_kernel<<<grid_e, 256, ED_SMEM>>>(ei, ea, w1a, E, ntiles_e);
    node_mma_kernel<<<ntiles_n, 256, ND_SMEM>>>(w1b, b1b, w2a, w2b, b2b, out, N);
}